// round 10
// baseline (speedup 1.0000x reference)
#include <cuda_runtime.h>
#include <cuda_fp16.h>

#define NMAX 100000
#define EMAX 1600000
#define HDIM 64
#define NGROUP 8

// ---------------- device scratch (no allocation allowed) --------------------
__device__ __align__(256) __half g_h16A[NMAX * HDIM];
__device__ __align__(256) __half g_h16B[NMAX * HDIM];
__device__ float g_sA[NMAX], g_dA[NMAX];
__device__ float g_sB[NMAX], g_dB[NMAX];
__device__ int   g_cnt[NMAX + 1];     // histogram, later scatter cursor
__device__ int   g_offs[NMAX + 1];    // CSR row offsets (by dst)
__device__ int   g_blksum[256];
__device__ int   g_csr[EMAX];         // src indices sorted by dst
__device__ float g_vnsum[NGROUP * HDIM];

// ---------------------------------------------------------------------------
// CSR build: zero -> histogram -> scanA -> scanC(+blk prefix) -> scatter
// ---------------------------------------------------------------------------
__global__ void zero_kernel(int N) {
    int i = blockIdx.x * blockDim.x + threadIdx.x;
    if (i <= N) g_cnt[i] = 0;
    if (i < NGROUP * HDIM) g_vnsum[i] = 0.f;
}

__global__ void hist_kernel(const int* __restrict__ ei, int E) {
    int e = blockIdx.x * blockDim.x + threadIdx.x;
    if (e < E) atomicAdd(&g_cnt[ei[E + e]], 1);
}

__global__ void scanA_kernel(int N) {
    __shared__ int wsum[8];
    int t = threadIdx.x;
    int base = blockIdx.x * 1024;
    int v[4]; int s = 0;
#pragma unroll
    for (int j = 0; j < 4; j++) {
        int idx = base + t * 4 + j;
        v[j] = (idx < N) ? g_cnt[idx] : 0;
        s += v[j];
    }
    int lane = t & 31, wid = t >> 5;
    int inc = s;
#pragma unroll
    for (int o = 1; o < 32; o <<= 1) {
        int y = __shfl_up_sync(0xffffffffu, inc, o);
        if (lane >= o) inc += y;
    }
    if (lane == 31) wsum[wid] = inc;
    __syncthreads();
    if (t < 8) {
        int x = wsum[t];
#pragma unroll
        for (int o = 1; o < 8; o <<= 1) {
            int y = __shfl_up_sync(0xffu, x, o);
            if (t >= o) x += y;
        }
        wsum[t] = x;
    }
    __syncthreads();
    int excl = inc - s + (wid > 0 ? wsum[wid - 1] : 0);
#pragma unroll
    for (int j = 0; j < 4; j++) {
        int idx = base + t * 4 + j;
        if (idx < N) g_offs[idx] = excl;
        excl += v[j];
    }
    if (t == 255) g_blksum[blockIdx.x] = wsum[7];
}

__global__ void scanC_kernel(int N, int E) {
    __shared__ int sbase;
    int myblk = (blockIdx.x * 256) >> 10;
    if (threadIdx.x < 32) {
        int acc = 0;
        for (int j = threadIdx.x; j < myblk; j += 32) acc += g_blksum[j];
#pragma unroll
        for (int o = 16; o >= 1; o >>= 1) acc += __shfl_xor_sync(0xffffffffu, acc, o);
        if (threadIdx.x == 0) sbase = acc;
    }
    __syncthreads();
    int i = blockIdx.x * 256 + threadIdx.x;
    if (i < N) {
        int o = g_offs[i] + sbase;
        g_offs[i] = o;
        g_cnt[i] = o;
    }
    if (i == 0) g_offs[N] = E;
}

__global__ void scatter_kernel(const int* __restrict__ ei, int E) {
    int e = blockIdx.x * blockDim.x + threadIdx.x;
    if (e >= E) return;
    int src = ei[e];
    int dst = ei[E + e];
    int pos = atomicAdd(&g_cnt[dst], 1);
    g_csr[pos] = src;
}

// ---------------------------------------------------------------------------
// Layer 0 linear: h = x(N,3) @ W0(3,64) -> g_h16A; also sA/dA dots
// ---------------------------------------------------------------------------
__global__ void lin0_kernel(const float* __restrict__ x,
                            const float* __restrict__ W0,
                            const float* __restrict__ as0,
                            const float* __restrict__ ad0, int N) {
    __shared__ float Ws[3 * 64];
    __shared__ float hs[64][65];
    int t = threadIdx.x;
    int c = t & 63, r = t >> 6;
    int n0 = blockIdx.x * 64;
    if (t < 192) Ws[t] = W0[t];
    __syncthreads();
#pragma unroll
    for (int i = 0; i < 16; i++) {
        int nl = r * 16 + i;
        int n = n0 + nl;
        float acc = 0.f;
        if (n < N) {
            float x0 = x[n * 3 + 0], x1 = x[n * 3 + 1], x2 = x[n * 3 + 2];
            acc = x0 * Ws[c] + x1 * Ws[64 + c] + x2 * Ws[128 + c];
            g_h16A[n * 64 + c] = __float2half_rn(acc);
        }
        hs[nl][c] = acc;
    }
    __syncthreads();
    if (t < 64) {
        int n = n0 + t;
        if (n < N) {
            float sv = 0.f, dv = 0.f;
#pragma unroll
            for (int k = 0; k < 64; k++) {
                float hv = hs[t][k];
                sv += hv * as0[k];
                dv += hv * ad0[k];
            }
            g_sA[n] = sv;
            g_dA[n] = dv;
        }
    }
}

// ---------------------------------------------------------------------------
// Fused gather + tensor-core GEMM. dir=0: read A / write B; dir=1: B -> A.
// Phase 1: each of 8 warps gathers 16 dst nodes (R8 staged scheme) straight
// into the fp16 smem A-tile (bias + leaky applied).
// Phase 2: HMMA GEMM h=act@W, fused s/d dots, write next-layer mirrors.
// ---------------------------------------------------------------------------
__global__ void gat_lin_kernel(const float* __restrict__ bias,
                               const float* __restrict__ W,
                               const float* __restrict__ avs,
                               const float* __restrict__ avd,
                               int N, int dir) {
    __shared__ __half xh[128][72];
    __shared__ __half Wt[64][72];
    __shared__ float as_sh[64], ad_sh[64];
    __shared__ int2 stage[8][32];
    int t = threadIdx.x;
    int n0 = blockIdx.x * 128;
    const __half* __restrict__ hsrc = dir ? g_h16B : g_h16A;
    __half* __restrict__ hdst = dir ? g_h16A : g_h16B;
    const float* __restrict__ ssrc = dir ? g_sB : g_sA;
    const float* __restrict__ dsrc = dir ? g_dB : g_dA;
    float* __restrict__ sdst = dir ? g_sA : g_sB;
    float* __restrict__ ddst = dir ? g_dA : g_dB;

    // load W (fp16, transposed) + attention vectors
#pragma unroll
    for (int j = 0; j < 16; j++) {
        int idx = j * 256 + t;
        int k = idx >> 6, n = idx & 63;
        Wt[n][k] = __float2half_rn(W[idx]);
    }
    if (t < 64) { as_sh[t] = avs[t]; ad_sh[t] = avd[t]; }

    // ---- Phase 1: gather 16 nodes per warp into xh ----
    int wl = t >> 5, lane = t & 31;
    float b0v = bias[lane * 2], b1v = bias[lane * 2 + 1];
    for (int i = 0; i < 16; i++) {
        int row = wl * 16 + i;
        int dst = n0 + row;
        if (dst >= N) {
            *(__half2*)&xh[row][lane * 2] = __floats2half2_rn(0.f, 0.f);
            continue;
        }
        float dv = dsrc[dst];
        float lg = ssrc[dst] + dv;
        lg = lg > 0.f ? lg : 0.2f * lg;
        float pself = __expf(lg);
        float2 h2 = __half22float2(*(const __half2*)(hsrc + dst * 64 + lane * 2));
        float ax = pself * h2.x, ay = pself * h2.y;
        float denl = (lane == 0) ? pself : 0.f;
        int e0 = g_offs[dst], e1 = g_offs[dst + 1];
        for (int base = e0; base < e1; base += 32) {
            int cnt = e1 - base;
            if (cnt > 32) cnt = 32;
            int idx = 0;
            float pv = 0.f;
            if (lane < cnt) {
                idx = g_csr[base + lane];
                float sv = ssrc[idx];
                float l = sv + dv;
                l = l > 0.f ? l : 0.2f * l;
                pv = __expf(l);
            }
            denl += pv;
            stage[wl][lane] = make_int2(idx, __float_as_int(pv));
            __syncwarp();
            int j = 0;
            for (; j + 3 < cnt; j += 4) {
                int2 v0 = stage[wl][j],     v1 = stage[wl][j + 1];
                int2 v2 = stage[wl][j + 2], v3 = stage[wl][j + 3];
                float2 f0 = __half22float2(*(const __half2*)(hsrc + v0.x * 64 + lane * 2));
                float2 f1 = __half22float2(*(const __half2*)(hsrc + v1.x * 64 + lane * 2));
                float2 f2 = __half22float2(*(const __half2*)(hsrc + v2.x * 64 + lane * 2));
                float2 f3 = __half22float2(*(const __half2*)(hsrc + v3.x * 64 + lane * 2));
                float p0 = __int_as_float(v0.y), p1 = __int_as_float(v1.y);
                float p2 = __int_as_float(v2.y), p3 = __int_as_float(v3.y);
                ax += p0 * f0.x + p1 * f1.x + p2 * f2.x + p3 * f3.x;
                ay += p0 * f0.y + p1 * f1.y + p2 * f2.y + p3 * f3.y;
            }
            for (; j < cnt; j++) {
                int2 v = stage[wl][j];
                float2 f = __half22float2(*(const __half2*)(hsrc + v.x * 64 + lane * 2));
                float pj = __int_as_float(v.y);
                ax += pj * f.x;
                ay += pj * f.y;
            }
            __syncwarp();
        }
#pragma unroll
        for (int o = 16; o >= 1; o >>= 1) denl += __shfl_xor_sync(0xffffffffu, denl, o);
        float inv = 1.f / denl;
        float ox = ax * inv + b0v;
        float oy = ay * inv + b1v;
        ox = ox > 0.f ? ox : 0.01f * ox;
        oy = oy > 0.f ? oy : 0.01f * oy;
        *(__half2*)&xh[row][lane * 2] = __floats2half2_rn(ox, oy);
    }
    __syncthreads();

    // ---- Phase 2: HMMA GEMM ----
    int wid = t >> 5;
    int g = lane >> 2, tg = lane & 3;
    int nw = wid * 16;
    float acc[8][4];
#pragma unroll
    for (int i = 0; i < 8; i++)
#pragma unroll
        for (int j = 0; j < 4; j++) acc[i][j] = 0.f;

#pragma unroll
    for (int s = 0; s < 8; s++) {
        unsigned a0 = *(const unsigned*)&xh[nw + g][s * 8 + tg * 2];
        unsigned a1 = *(const unsigned*)&xh[nw + g + 8][s * 8 + tg * 2];
#pragma unroll
        for (int nt = 0; nt < 8; nt++) {
            unsigned b = *(const unsigned*)&Wt[nt * 8 + g][s * 8 + tg * 2];
            asm volatile(
                "mma.sync.aligned.m16n8k8.row.col.f32.f16.f16.f32 "
                "{%0,%1,%2,%3}, {%4,%5}, {%6}, {%0,%1,%2,%3};"
                : "+f"(acc[nt][0]), "+f"(acc[nt][1]),
                  "+f"(acc[nt][2]), "+f"(acc[nt][3])
                : "r"(a0), "r"(a1), "r"(b));
        }
    }

    float ps0 = 0.f, ps1 = 0.f, pd0 = 0.f, pd1 = 0.f;
#pragma unroll
    for (int nt = 0; nt < 8; nt++) {
        float2 a = *(const float2*)&as_sh[nt * 8 + tg * 2];
        float2 d = *(const float2*)&ad_sh[nt * 8 + tg * 2];
        ps0 += acc[nt][0] * a.x + acc[nt][1] * a.y;
        ps1 += acc[nt][2] * a.x + acc[nt][3] * a.y;
        pd0 += acc[nt][0] * d.x + acc[nt][1] * d.y;
        pd1 += acc[nt][2] * d.x + acc[nt][3] * d.y;
    }
#pragma unroll
    for (int o = 1; o <= 2; o <<= 1) {
        ps0 += __shfl_xor_sync(0xffffffffu, ps0, o);
        ps1 += __shfl_xor_sync(0xffffffffu, ps1, o);
        pd0 += __shfl_xor_sync(0xffffffffu, pd0, o);
        pd1 += __shfl_xor_sync(0xffffffffu, pd1, o);
    }
    if (tg == 0) {
        int n1 = n0 + nw + g, n2 = n1 + 8;
        if (n1 < N) { sdst[n1] = ps0; ddst[n1] = pd0; }
        if (n2 < N) { sdst[n2] = ps1; ddst[n2] = pd1; }
    }

    // stage fp16 result and copy out vectorized
    __syncwarp();
#pragma unroll
    for (int nt = 0; nt < 8; nt++) {
        *(__half2*)&xh[nw + g][nt * 8 + tg * 2]     = __floats2half2_rn(acc[nt][0], acc[nt][1]);
        *(__half2*)&xh[nw + g + 8][nt * 8 + tg * 2] = __floats2half2_rn(acc[nt][2], acc[nt][3]);
    }
    __syncwarp();
#pragma unroll
    for (int j = 0; j < 4; j++) {
        int cid = j * 32 + lane;
        int r = nw + (cid >> 3);
        int c = (cid & 7) * 8;
        uint4 v = *(const uint4*)&xh[r][c];
        int n = n0 + r;
        if (n < N) *(uint4*)(hdst + (long long)n * 64 + c) = v;
    }
}

// ---------------------------------------------------------------------------
// Fused gather(layer 3, reads A) + output head + vn pooling. 256 threads.
// ---------------------------------------------------------------------------
__global__ void gat_last_kernel(const float* __restrict__ bias,
                                const float* __restrict__ out_w,
                                const float* __restrict__ out_b,
                                const int* __restrict__ batch,
                                float* __restrict__ out1, int N) {
    __shared__ float hs[128][65];
    __shared__ float ow[64][20];
    __shared__ float ob[20];
    __shared__ int bsh[128];
    __shared__ int2 stage[8][32];
    int t = threadIdx.x;
    int n0 = blockIdx.x * 128;
    for (int idx = t; idx < 64 * 20; idx += 256) ow[idx / 20][idx % 20] = out_w[idx];
    if (t < 20) ob[t] = out_b[t];
    if (t < 128) {
        int n = n0 + t;
        bsh[t] = (n < N) ? batch[n] : -1;
    }

    // ---- Phase 1: gather 16 nodes per warp into hs (fp32) ----
    int wl = t >> 5, lane = t & 31;
    float b0v = bias[lane * 2], b1v = bias[lane * 2 + 1];
    for (int i = 0; i < 16; i++) {
        int row = wl * 16 + i;
        int dst = n0 + row;
        if (dst >= N) {
            hs[row][lane * 2] = 0.f;
            hs[row][lane * 2 + 1] = 0.f;
            continue;
        }
        float dv = g_dA[dst];
        float lg = g_sA[dst] + dv;
        lg = lg > 0.f ? lg : 0.2f * lg;
        float pself = __expf(lg);
        float2 h2 = __half22float2(*(const __half2*)(g_h16A + dst * 64 + lane * 2));
        float ax = pself * h2.x, ay = pself * h2.y;
        float denl = (lane == 0) ? pself : 0.f;
        int e0 = g_offs[dst], e1 = g_offs[dst + 1];
        for (int base = e0; base < e1; base += 32) {
            int cnt = e1 - base;
            if (cnt > 32) cnt = 32;
            int idx = 0;
            float pv = 0.f;
            if (lane < cnt) {
                idx = g_csr[base + lane];
                float sv = g_sA[idx];
                float l = sv + dv;
                l = l > 0.f ? l : 0.2f * l;
                pv = __expf(l);
            }
            denl += pv;
            stage[wl][lane] = make_int2(idx, __float_as_int(pv));
            __syncwarp();
            int j = 0;
            for (; j + 3 < cnt; j += 4) {
                int2 v0 = stage[wl][j],     v1 = stage[wl][j + 1];
                int2 v2 = stage[wl][j + 2], v3 = stage[wl][j + 3];
                float2 f0 = __half22float2(*(const __half2*)(g_h16A + v0.x * 64 + lane * 2));
                float2 f1 = __half22float2(*(const __half2*)(g_h16A + v1.x * 64 + lane * 2));
                float2 f2 = __half22float2(*(const __half2*)(g_h16A + v2.x * 64 + lane * 2));
                float2 f3 = __half22float2(*(const __half2*)(g_h16A + v3.x * 64 + lane * 2));
                float p0 = __int_as_float(v0.y), p1 = __int_as_float(v1.y);
                float p2 = __int_as_float(v2.y), p3 = __int_as_float(v3.y);
                ax += p0 * f0.x + p1 * f1.x + p2 * f2.x + p3 * f3.x;
                ay += p0 * f0.y + p1 * f1.y + p2 * f2.y + p3 * f3.y;
            }
            for (; j < cnt; j++) {
                int2 v = stage[wl][j];
                float2 f = __half22float2(*(const __half2*)(g_h16A + v.x * 64 + lane * 2));
                float pj = __int_as_float(v.y);
                ax += pj * f.x;
                ay += pj * f.y;
            }
            __syncwarp();
        }
#pragma unroll
        for (int o = 16; o >= 1; o >>= 1) denl += __shfl_xor_sync(0xffffffffu, denl, o);
        float inv = 1.f / denl;
        float ox = ax * inv + b0v;
        float oy = ay * inv + b1v;
        ox = ox > 0.f ? ox : 0.01f * ox;
        oy = oy > 0.f ? oy : 0.01f * oy;
        hs[row][lane * 2] = ox;
        hs[row][lane * 2 + 1] = oy;
    }
    __syncthreads();

    // ---- Phase 2: out1 = hs @ out_w + out_b  (2 nodes x 5 cols / thread) ----
    int ngq = t >> 2, cgq = t & 3;   // 64 node groups x 4 col groups
    float acc[2][5];
#pragma unroll
    for (int i = 0; i < 2; i++)
#pragma unroll
        for (int j = 0; j < 5; j++) acc[i][j] = ob[cgq * 5 + j];
#pragma unroll 8
    for (int k = 0; k < 64; k++) {
        float wv[5];
#pragma unroll
        for (int j = 0; j < 5; j++) wv[j] = ow[k][cgq * 5 + j];
#pragma unroll
        for (int i = 0; i < 2; i++) {
            float hv = hs[ngq * 2 + i][k];
#pragma unroll
            for (int j = 0; j < 5; j++) acc[i][j] += hv * wv[j];
        }
    }
#pragma unroll
    for (int i = 0; i < 2; i++) {
        int n = n0 + ngq * 2 + i;
        if (n < N) {
#pragma unroll
            for (int j = 0; j < 5; j++) out1[n * 20 + cgq * 5 + j] = acc[i][j];
        }
    }
    // vn pooling: threads 0..63 own one column each, run-length over block
    if (t < 64) {
        int nend = N - n0;
        if (nend > 128) nend = 128;
        if (nend > 0) {
            int curg = bsh[0];
            float run = 0.f;
            for (int nl = 0; nl < nend; nl++) {
                int g = bsh[nl];
                if (g != curg) {
                    atomicAdd(&g_vnsum[curg * 64 + t], run);
                    run = 0.f;
                    curg = g;
                }
                run += hs[nl][t];
            }
            atomicAdd(&g_vnsum[curg * 64 + t], run);
        }
    }
}

// ---------------------------------------------------------------------------
// Virtual-node MLP head: 4 layers on [8,64] -> [8,20]. One block.
// ---------------------------------------------------------------------------
__global__ void vn_mlp_kernel(const float* __restrict__ vn_emb0,
                              const float* __restrict__ w1, const float* __restrict__ bb1,
                              const float* __restrict__ w2, const float* __restrict__ bb2,
                              const float* __restrict__ w3, const float* __restrict__ bb3,
                              const float* __restrict__ w4, const float* __restrict__ bb4,
                              float* __restrict__ outvn) {
    __shared__ float a[NGROUP][64], tmp[NGROUP][64];
    int t = threadIdx.x;  // 512
    int g = t >> 6, c = t & 63;
    a[g][c] = g_vnsum[g * 64 + c] + vn_emb0[c];
    __syncthreads();
    float s = bb1[c];
    for (int k = 0; k < 64; k++) s += a[g][k] * w1[k * 64 + c];
    tmp[g][c] = fmaxf(s, 0.f);
    __syncthreads();
    s = bb2[c];
    for (int k = 0; k < 64; k++) s += tmp[g][k] * w2[k * 64 + c];
    a[g][c] = fmaxf(s, 0.f);
    __syncthreads();
    s = bb3[c];
    for (int k = 0; k < 64; k++) s += a[g][k] * w3[k * 64 + c];
    tmp[g][c] = fmaxf(s, 0.f);
    __syncthreads();
    if (c < 20) {
        s = bb4[c];
        for (int k = 0; k < 64; k++) s += tmp[g][k] * w4[k * 20 + c];
        outvn[g * 20 + c] = fmaxf(s, 0.f);
    }
}

// ---------------------------------------------------------------------------
extern "C" void kernel_launch(void* const* d_in, const int* in_sizes, int n_in,
                              void* d_out, int out_size) {
    const float* x      = (const float*)d_in[0];
    const int*   ei     = (const int*)d_in[1];
    const int*   batch  = (const int*)d_in[2];
    const float* W0     = (const float*)d_in[3];
    const float* as0    = (const float*)d_in[4];
    const float* ad0    = (const float*)d_in[5];
    const float* b0     = (const float*)d_in[6];
    const float* W1     = (const float*)d_in[7];
    const float* as1    = (const float*)d_in[8];
    const float* ad1    = (const float*)d_in[9];
    const float* b1     = (const float*)d_in[10];
    const float* W2     = (const float*)d_in[11];
    const float* as2    = (const float*)d_in[12];
    const float* ad2    = (const float*)d_in[13];
    const float* b2     = (const float*)d_in[14];
    const float* vn_emb0= (const float*)d_in[15];
    const float* m1_w1  = (const float*)d_in[16];
    const float* m1_b1  = (const float*)d_in[17];
    const float* m1_w2  = (const float*)d_in[18];
    const float* m1_b2  = (const float*)d_in[19];
    const float* mf_w1  = (const float*)d_in[20];
    const float* mf_b1  = (const float*)d_in[21];
    const float* mf_w2  = (const float*)d_in[22];
    const float* mf_b2  = (const float*)d_in[23];
    const float* out_w  = (const float*)d_in[24];
    const float* out_b  = (const float*)d_in[25];

    int N = in_sizes[0] / 3;
    int E = in_sizes[1] / 2;
    float* out1 = (float*)d_out;
    float* outvn = out1 + (long long)N * 20;

    int nblk64  = (N + 63) / 64;
    int nblk128 = (N + 127) / 128;
    int eblk    = (E + 255) / 256;
    int NB      = (N + 1023) / 1024;

    // CSR build (graph shared by all 3 layers)
    zero_kernel<<<(N + 256) / 256, 256>>>(N);
    hist_kernel<<<eblk, 256>>>(ei, E);
    scanA_kernel<<<NB, 256>>>(N);
    scanC_kernel<<<(N + 255) / 256, 256>>>(N, E);
    scatter_kernel<<<eblk, 256>>>(ei, E);

    // GNN layers (fused gather+GEMM, ping-pong A<->B)
    lin0_kernel<<<nblk64, 256>>>(x, W0, as0, ad0, N);
    gat_lin_kernel<<<nblk128, 256>>>(b0, W1, as1, ad1, N, 0);  // A -> B
    gat_lin_kernel<<<nblk128, 256>>>(b1, W2, as2, ad2, N, 1);  // B -> A
    gat_last_kernel<<<nblk128, 256>>>(b2, out_w, out_b, batch, out1, N);  // reads A
    vn_mlp_kernel<<<1, 512>>>(vn_emb0, m1_w1, m1_b1, m1_w2, m1_b2,
                              mf_w1, mf_b1, mf_w2, mf_b2, outvn);
}

// round 11
// speedup vs baseline: 1.6452x; 1.6452x over previous
#include <cuda_runtime.h>
#include <cuda_fp16.h>

#define NMAX 100000
#define EMAX 1600000
#define HDIM 64
#define NGROUP 8

// ---------------- device scratch (no allocation allowed) --------------------
__device__ __align__(256) __half g_h16[NMAX * HDIM];  // fp16 mirror for gathers
__device__ __align__(256) float g_hB[NMAX * HDIM];    // fp32 gather output
__device__ float g_s[NMAX];
__device__ float g_d[NMAX];
__device__ int   g_cnt[NMAX + 1];     // histogram, later scatter cursor
__device__ int   g_offs[NMAX + 1];    // CSR row offsets (by dst)
__device__ int   g_blksum[256];
__device__ int   g_csr[EMAX];         // src indices sorted by dst
__device__ float g_vnsum[NGROUP * HDIM];

// ---------------------------------------------------------------------------
// CSR build: zero -> histogram -> scanA -> scanC(+blk prefix) -> scatter
// ---------------------------------------------------------------------------
__global__ void zero_kernel(int N) {
    int i = blockIdx.x * blockDim.x + threadIdx.x;
    if (i <= N) g_cnt[i] = 0;
    if (i < NGROUP * HDIM) g_vnsum[i] = 0.f;
}

__global__ void hist_kernel(const int* __restrict__ ei, int E) {
    int e = blockIdx.x * blockDim.x + threadIdx.x;
    if (e < E) atomicAdd(&g_cnt[ei[E + e]], 1);
}

// per-block exclusive scan of g_cnt (1024 elements / block of 256 threads)
__global__ void scanA_kernel(int N) {
    __shared__ int wsum[8];
    int t = threadIdx.x;
    int base = blockIdx.x * 1024;
    int v[4]; int s = 0;
#pragma unroll
    for (int j = 0; j < 4; j++) {
        int idx = base + t * 4 + j;
        v[j] = (idx < N) ? g_cnt[idx] : 0;
        s += v[j];
    }
    int lane = t & 31, wid = t >> 5;
    int inc = s;
#pragma unroll
    for (int o = 1; o < 32; o <<= 1) {
        int y = __shfl_up_sync(0xffffffffu, inc, o);
        if (lane >= o) inc += y;
    }
    if (lane == 31) wsum[wid] = inc;
    __syncthreads();
    if (t < 8) {
        int x = wsum[t];
#pragma unroll
        for (int o = 1; o < 8; o <<= 1) {
            int y = __shfl_up_sync(0xffu, x, o);
            if (t >= o) x += y;
        }
        wsum[t] = x;
    }
    __syncthreads();
    int excl = inc - s + (wid > 0 ? wsum[wid - 1] : 0);
#pragma unroll
    for (int j = 0; j < 4; j++) {
        int idx = base + t * 4 + j;
        if (idx < N) g_offs[idx] = excl;
        excl += v[j];
    }
    if (t == 255) g_blksum[blockIdx.x] = wsum[7];
}

// adds cross-block prefix (computed in-kernel by warp 0) and finalizes offsets
__global__ void scanC_kernel(int N, int E) {
    __shared__ int sbase;
    int myblk = (blockIdx.x * 256) >> 10;
    if (threadIdx.x < 32) {
        int acc = 0;
        for (int j = threadIdx.x; j < myblk; j += 32) acc += g_blksum[j];
#pragma unroll
        for (int o = 16; o >= 1; o >>= 1) acc += __shfl_xor_sync(0xffffffffu, acc, o);
        if (threadIdx.x == 0) sbase = acc;
    }
    __syncthreads();
    int i = blockIdx.x * 256 + threadIdx.x;
    if (i < N) {
        int o = g_offs[i] + sbase;
        g_offs[i] = o;
        g_cnt[i] = o;   // scatter cursor
    }
    if (i == 0) g_offs[N] = E;
}

__global__ void scatter_kernel(const int* __restrict__ ei, int E) {
    int e = blockIdx.x * blockDim.x + threadIdx.x;
    if (e >= E) return;
    int src = ei[e];
    int dst = ei[E + e];
    int pos = atomicAdd(&g_cnt[dst], 1);
    g_csr[pos] = src;
}

// ---------------------------------------------------------------------------
// Layer 0 linear: h = x(N,3) @ W0(3,64) -> g_h16; also s = h.as, d = h.ad
// ---------------------------------------------------------------------------
__global__ void lin0_kernel(const float* __restrict__ x,
                            const float* __restrict__ W0,
                            const float* __restrict__ as0,
                            const float* __restrict__ ad0, int N) {
    __shared__ float Ws[3 * 64];
    __shared__ float hs[64][65];
    int t = threadIdx.x;
    int c = t & 63, r = t >> 6;
    int n0 = blockIdx.x * 64;
    if (t < 192) Ws[t] = W0[t];
    __syncthreads();
#pragma unroll
    for (int i = 0; i < 16; i++) {
        int nl = r * 16 + i;
        int n = n0 + nl;
        float acc = 0.f;
        if (n < N) {
            float x0 = x[n * 3 + 0], x1 = x[n * 3 + 1], x2 = x[n * 3 + 2];
            acc = x0 * Ws[c] + x1 * Ws[64 + c] + x2 * Ws[128 + c];
            g_h16[n * 64 + c] = __float2half_rn(acc);
        }
        hs[nl][c] = acc;
    }
    __syncthreads();
    if (t < 64) {
        int n = n0 + t;
        if (n < N) {
            float sv = 0.f, dv = 0.f;
#pragma unroll
            for (int k = 0; k < 64; k++) {
                float hv = hs[t][k];
                sv += hv * as0[k];
                dv += hv * ad0[k];
            }
            g_s[n] = sv;
            g_d[n] = dv;
        }
    }
}

// ---------------------------------------------------------------------------
// Gather attention pass (g_h16 -> g_hB): one warp per dst node.
// Staging as in R8 (each lane computes p for one edge). Broadcast phase now
// splits the warp into two halves working on the SAME node: lanes 0-15 take
// even staged edges, lanes 16-31 odd ones, each lane covering 8B (4 halves)
// of the feature row -> one LDG.64/LDS.64 serves TWO edges. Control flow is
// warp-uniform (same node). Stage entries >= cnt carry pv=0 so the odd-half
// read at odd cnt contributes zero. Halves merged by one shfl_xor(16).
// (max-shift skipped: softmax shift-invariant, logits are O(0.1))
// ---------------------------------------------------------------------------
__global__ void gather_kernel(const float* __restrict__ bias, int N) {
    __shared__ int2 stage[8][32];
    int w = (blockIdx.x * blockDim.x + threadIdx.x) >> 5;
    int lane = threadIdx.x & 31;
    int wl = threadIdx.x >> 5;
    if (w >= N) return;
    int dst = w;
    int l16 = lane & 15;
    int hi = lane >> 4;          // 0: even edges, 1: odd edges
    float dv = g_d[dst];
    // self loop
    float lg = g_s[dst] + dv;
    lg = lg > 0.f ? lg : 0.2f * lg;
    float pself = __expf(lg);
    float a0 = 0.f, a1 = 0.f, a2 = 0.f, a3 = 0.f;
    if (hi == 0) {
        uint2 r = *(const uint2*)(g_h16 + dst * 64 + l16 * 4);
        float2 fA = __half22float2(*(__half2*)&r.x);
        float2 fB = __half22float2(*(__half2*)&r.y);
        a0 = pself * fA.x; a1 = pself * fA.y;
        a2 = pself * fB.x; a3 = pself * fB.y;
    }
    float denl = (lane == 0) ? pself : 0.f;
    int e0 = g_offs[dst], e1 = g_offs[dst + 1];
    for (int base = e0; base < e1; base += 32) {
        int cnt = e1 - base;
        if (cnt > 32) cnt = 32;
        int idx = 0;
        float pv = 0.f;
        if (lane < cnt) {
            idx = g_csr[base + lane];
            float sv = g_s[idx];
            float l = sv + dv;
            l = l > 0.f ? l : 0.2f * l;
            pv = __expf(l);
        }
        denl += pv;
        stage[wl][lane] = make_int2(idx, __float_as_int(pv));
        __syncwarp();
        int j = 0;
        for (; j + 7 < cnt; j += 8) {     // 4 pairs = 8 edges per iter
            int2 v0 = stage[wl][j + hi];
            int2 v1 = stage[wl][j + 2 + hi];
            int2 v2 = stage[wl][j + 4 + hi];
            int2 v3 = stage[wl][j + 6 + hi];
            uint2 r0 = *(const uint2*)(g_h16 + v0.x * 64 + l16 * 4);
            uint2 r1 = *(const uint2*)(g_h16 + v1.x * 64 + l16 * 4);
            uint2 r2 = *(const uint2*)(g_h16 + v2.x * 64 + l16 * 4);
            uint2 r3 = *(const uint2*)(g_h16 + v3.x * 64 + l16 * 4);
            float p0 = __int_as_float(v0.y), p1 = __int_as_float(v1.y);
            float p2 = __int_as_float(v2.y), p3 = __int_as_float(v3.y);
            float2 fA, fB;
            fA = __half22float2(*(__half2*)&r0.x); fB = __half22float2(*(__half2*)&r0.y);
            a0 += p0 * fA.x; a1 += p0 * fA.y; a2 += p0 * fB.x; a3 += p0 * fB.y;
            fA = __half22float2(*(__half2*)&r1.x); fB = __half22float2(*(__half2*)&r1.y);
            a0 += p1 * fA.x; a1 += p1 * fA.y; a2 += p1 * fB.x; a3 += p1 * fB.y;
            fA = __half22float2(*(__half2*)&r2.x); fB = __half22float2(*(__half2*)&r2.y);
            a0 += p2 * fA.x; a1 += p2 * fA.y; a2 += p2 * fB.x; a3 += p2 * fB.y;
            fA = __half22float2(*(__half2*)&r3.x); fB = __half22float2(*(__half2*)&r3.y);
            a0 += p3 * fA.x; a1 += p3 * fA.y; a2 += p3 * fB.x; a3 += p3 * fB.y;
        }
        for (; j < cnt; j += 2) {         // pad entries have pv = 0
            int2 v = stage[wl][j + hi];
            uint2 r = *(const uint2*)(g_h16 + v.x * 64 + l16 * 4);
            float p = __int_as_float(v.y);
            float2 fA = __half22float2(*(__half2*)&r.x);
            float2 fB = __half22float2(*(__half2*)&r.y);
            a0 += p * fA.x; a1 += p * fA.y; a2 += p * fB.x; a3 += p * fB.y;
        }
        __syncwarp();
    }
    // merge the two halves (same columns)
    a0 += __shfl_xor_sync(0xffffffffu, a0, 16);
    a1 += __shfl_xor_sync(0xffffffffu, a1, 16);
    a2 += __shfl_xor_sync(0xffffffffu, a2, 16);
    a3 += __shfl_xor_sync(0xffffffffu, a3, 16);
#pragma unroll
    for (int o = 16; o >= 1; o >>= 1) denl += __shfl_xor_sync(0xffffffffu, denl, o);
    if (hi == 0) {
        float inv = 1.f / denl;
        float4 bv = *(const float4*)(bias + l16 * 4);
        float o0 = a0 * inv + bv.x;
        float o1 = a1 * inv + bv.y;
        float o2 = a2 * inv + bv.z;
        float o3 = a3 * inv + bv.w;
        o0 = o0 > 0.f ? o0 : 0.01f * o0;
        o1 = o1 > 0.f ? o1 : 0.01f * o1;
        o2 = o2 > 0.f ? o2 : 0.01f * o2;
        o3 = o3 > 0.f ? o3 : 0.01f * o3;
        *(float4*)(g_hB + dst * 64 + l16 * 4) = make_float4(o0, o1, o2, o3);
    }
}

// ---------------------------------------------------------------------------
// Tensor-core GEMM (g_hB -> g_h16): h = x(128,64) @ W(64,64) via
// mma.sync.m16n8k8.f32.f16.f16.f32. Block 256 = 8 warps x 16 nodes.
// ---------------------------------------------------------------------------
__global__ void fin_lin_kernel(const float* __restrict__ W,
                               const float* __restrict__ avs,
                               const float* __restrict__ avd, int N) {
    __shared__ __half xh[128][72];
    __shared__ __half Wt[64][72];
    __shared__ float as_sh[64], ad_sh[64];
    int t = threadIdx.x;
    int n0 = blockIdx.x * 128;
    // W -> fp16 transposed
#pragma unroll
    for (int j = 0; j < 16; j++) {
        int idx = j * 256 + t;
        int k = idx >> 6, n = idx & 63;
        Wt[n][k] = __float2half_rn(W[idx]);
    }
    if (t < 64) { as_sh[t] = avs[t]; ad_sh[t] = avd[t]; }
    // x (fp32 gather output) -> fp16 smem
#pragma unroll
    for (int j = 0; j < 8; j++) {
        int idx = j * 256 + t;            // float4 chunks over 128x64
        int nl = idx >> 4, c4 = (idx & 15) * 4;
        int n = n0 + nl;
        float4 v = (n < N) ? *(const float4*)(g_hB + (long long)n * 64 + c4)
                           : make_float4(0.f, 0.f, 0.f, 0.f);
        *(__half2*)&xh[nl][c4]     = __floats2half2_rn(v.x, v.y);
        *(__half2*)&xh[nl][c4 + 2] = __floats2half2_rn(v.z, v.w);
    }
    __syncthreads();

    int wid = t >> 5, lane = t & 31;
    int g = lane >> 2, tg = lane & 3;
    int nw = wid * 16;                     // warp's node base within block
    float acc[8][4];
#pragma unroll
    for (int i = 0; i < 8; i++)
#pragma unroll
        for (int j = 0; j < 4; j++) acc[i][j] = 0.f;

#pragma unroll
    for (int s = 0; s < 8; s++) {
        unsigned a0 = *(const unsigned*)&xh[nw + g][s * 8 + tg * 2];
        unsigned a1 = *(const unsigned*)&xh[nw + g + 8][s * 8 + tg * 2];
#pragma unroll
        for (int nt = 0; nt < 8; nt++) {
            unsigned b = *(const unsigned*)&Wt[nt * 8 + g][s * 8 + tg * 2];
            asm volatile(
                "mma.sync.aligned.m16n8k8.row.col.f32.f16.f16.f32 "
                "{%0,%1,%2,%3}, {%4,%5}, {%6}, {%0,%1,%2,%3};"
                : "+f"(acc[nt][0]), "+f"(acc[nt][1]),
                  "+f"(acc[nt][2]), "+f"(acc[nt][3])
                : "r"(a0), "r"(a1), "r"(b));
        }
    }

    // s/d dots from fp32 accumulators
    float ps0 = 0.f, ps1 = 0.f, pd0 = 0.f, pd1 = 0.f;
#pragma unroll
    for (int nt = 0; nt < 8; nt++) {
        float2 a = *(const float2*)&as_sh[nt * 8 + tg * 2];
        float2 d = *(const float2*)&ad_sh[nt * 8 + tg * 2];
        ps0 += acc[nt][0] * a.x + acc[nt][1] * a.y;
        ps1 += acc[nt][2] * a.x + acc[nt][3] * a.y;
        pd0 += acc[nt][0] * d.x + acc[nt][1] * d.y;
        pd1 += acc[nt][2] * d.x + acc[nt][3] * d.y;
    }
#pragma unroll
    for (int o = 1; o <= 2; o <<= 1) {
        ps0 += __shfl_xor_sync(0xffffffffu, ps0, o);
        ps1 += __shfl_xor_sync(0xffffffffu, ps1, o);
        pd0 += __shfl_xor_sync(0xffffffffu, pd0, o);
        pd1 += __shfl_xor_sync(0xffffffffu, pd1, o);
    }
    if (tg == 0) {
        int n1 = n0 + nw + g, n2 = n1 + 8;
        if (n1 < N) { g_s[n1] = ps0; g_d[n1] = pd0; }
        if (n2 < N) { g_s[n2] = ps1; g_d[n2] = pd1; }
    }

    // stage fp16 result into this warp's own xh rows, then vectorized copy out
#pragma unroll
    for (int nt = 0; nt < 8; nt++) {
        *(__half2*)&xh[nw + g][nt * 8 + tg * 2]     = __floats2half2_rn(acc[nt][0], acc[nt][1]);
        *(__half2*)&xh[nw + g + 8][nt * 8 + tg * 2] = __floats2half2_rn(acc[nt][2], acc[nt][3]);
    }
    __syncwarp();
#pragma unroll
    for (int j = 0; j < 4; j++) {
        int cid = j * 32 + lane;           // 128 uint4 chunks = 16 rows x 8
        int r = nw + (cid >> 3);
        int c = (cid & 7) * 8;
        uint4 v = *(const uint4*)&xh[r][c];
        int n = n0 + r;
        if (n < N) *(uint4*)(g_h16 + (long long)n * 64 + c) = v;
    }
}

// ---------------------------------------------------------------------------
// Final stage (reads g_hB): out1 = h @ out_w + out_b (4x5 register tile);
// vn run-length pooling (batch sorted). Block: 128 nodes, 128 threads.
// ---------------------------------------------------------------------------
__global__ void fin_last_kernel(const float* __restrict__ out_w,
                                const float* __restrict__ out_b,
                                const int* __restrict__ batch,
                                float* __restrict__ out1, int N) {
    __shared__ float hs[128][65];
    __shared__ float ow[64][20];
    __shared__ float ob[20];
    __shared__ int bsh[128];
    int t = threadIdx.x;
    int n0 = blockIdx.x * 128;
    for (int idx = t; idx < 64 * 20; idx += 128) ow[idx / 20][idx % 20] = out_w[idx];
    if (t < 20) ob[t] = out_b[t];
#pragma unroll
    for (int j = 0; j < 64; j++) {
        int idx = j * 128 + t;
        int nl = idx >> 6, c = idx & 63;
        int n = n0 + nl;
        hs[nl][c] = (n < N) ? g_hB[n * 64 + c] : 0.f;
    }
    {
        int n = n0 + t;
        bsh[t] = (n < N) ? batch[n] : -1;
    }
    __syncthreads();
    int ngq = t >> 2, cgq = t & 3;   // 32 node groups x 4 col groups
    float acc[4][5];
#pragma unroll
    for (int i = 0; i < 4; i++)
#pragma unroll
        for (int j = 0; j < 5; j++) acc[i][j] = ob[cgq * 5 + j];
#pragma unroll 8
    for (int k = 0; k < 64; k++) {
        float wv[5];
#pragma unroll
        for (int j = 0; j < 5; j++) wv[j] = ow[k][cgq * 5 + j];
#pragma unroll
        for (int i = 0; i < 4; i++) {
            float hv = hs[ngq * 4 + i][k];
#pragma unroll
            for (int j = 0; j < 5; j++) acc[i][j] += hv * wv[j];
        }
    }
#pragma unroll
    for (int i = 0; i < 4; i++) {
        int n = n0 + ngq * 4 + i;
        if (n < N) {
#pragma unroll
            for (int j = 0; j < 5; j++) out1[n * 20 + cgq * 5 + j] = acc[i][j];
        }
    }
    // vn pooling: threads 0..63 own one column each, run-length over block
    if (t < 64) {
        int nend = N - n0;
        if (nend > 128) nend = 128;
        if (nend > 0) {
            int curg = bsh[0];
            float run = 0.f;
            for (int nl = 0; nl < nend; nl++) {
                int g = bsh[nl];
                if (g != curg) {
                    atomicAdd(&g_vnsum[curg * 64 + t], run);
                    run = 0.f;
                    curg = g;
                }
                run += hs[nl][t];
            }
            atomicAdd(&g_vnsum[curg * 64 + t], run);
        }
    }
}

// ---------------------------------------------------------------------------
// Virtual-node MLP head: 4 layers on [8,64] -> [8,20]. One block.
// ---------------------------------------------------------------------------
__global__ void vn_mlp_kernel(const float* __restrict__ vn_emb0,
                              const float* __restrict__ w1, const float* __restrict__ bb1,
                              const float* __restrict__ w2, const float* __restrict__ bb2,
                              const float* __restrict__ w3, const float* __restrict__ bb3,
                              const float* __restrict__ w4, const float* __restrict__ bb4,
                              float* __restrict__ outvn) {
    __shared__ float a[NGROUP][64], tmp[NGROUP][64];
    int t = threadIdx.x;  // 512
    int g = t >> 6, c = t & 63;
    a[g][c] = g_vnsum[g * 64 + c] + vn_emb0[c];
    __syncthreads();
    float s = bb1[c];
    for (int k = 0; k < 64; k++) s += a[g][k] * w1[k * 64 + c];
    tmp[g][c] = fmaxf(s, 0.f);
    __syncthreads();
    s = bb2[c];
    for (int k = 0; k < 64; k++) s += tmp[g][k] * w2[k * 64 + c];
    a[g][c] = fmaxf(s, 0.f);
    __syncthreads();
    s = bb3[c];
    for (int k = 0; k < 64; k++) s += a[g][k] * w3[k * 64 + c];
    tmp[g][c] = fmaxf(s, 0.f);
    __syncthreads();
    if (c < 20) {
        s = bb4[c];
        for (int k = 0; k < 64; k++) s += tmp[g][k] * w4[k * 20 + c];
        outvn[g * 20 + c] = fmaxf(s, 0.f);
    }
}

// ---------------------------------------------------------------------------
extern "C" void kernel_launch(void* const* d_in, const int* in_sizes, int n_in,
                              void* d_out, int out_size) {
    const float* x      = (const float*)d_in[0];
    const int*   ei     = (const int*)d_in[1];
    const int*   batch  = (const int*)d_in[2];
    const float* W0     = (const float*)d_in[3];
    const float* as0    = (const float*)d_in[4];
    const float* ad0    = (const float*)d_in[5];
    const float* b0     = (const float*)d_in[6];
    const float* W1     = (const float*)d_in[7];
    const float* as1    = (const float*)d_in[8];
    const float* ad1    = (const float*)d_in[9];
    const float* b1     = (const float*)d_in[10];
    const float* W2     = (const float*)d_in[11];
    const float* as2    = (const float*)d_in[12];
    const float* ad2    = (const float*)d_in[13];
    const float* b2     = (const float*)d_in[14];
    const float* vn_emb0= (const float*)d_in[15];
    const float* m1_w1  = (const float*)d_in[16];
    const float* m1_b1  = (const float*)d_in[17];
    const float* m1_w2  = (const float*)d_in[18];
    const float* m1_b2  = (const float*)d_in[19];
    const float* mf_w1  = (const float*)d_in[20];
    const float* mf_b1  = (const float*)d_in[21];
    const float* mf_w2  = (const float*)d_in[22];
    const float* mf_b2  = (const float*)d_in[23];
    const float* out_w  = (const float*)d_in[24];
    const float* out_b  = (const float*)d_in[25];

    int N = in_sizes[0] / 3;
    int E = in_sizes[1] / 2;
    float* out1 = (float*)d_out;
    float* outvn = out1 + (long long)N * 20;

    int nblk64  = (N + 63) / 64;
    int nblk128 = (N + 127) / 128;
    int eblk    = (E + 255) / 256;
    int NB      = (N + 1023) / 1024;
    int gblk    = (N * 32 + 255) / 256;   // one full warp per node

    // CSR build (graph shared by all 3 layers)
    zero_kernel<<<(N + 256) / 256, 256>>>(N);
    hist_kernel<<<eblk, 256>>>(ei, E);
    scanA_kernel<<<NB, 256>>>(N);
    scanC_kernel<<<(N + 255) / 256, 256>>>(N, E);
    scatter_kernel<<<eblk, 256>>>(ei, E);

    // GNN layers (ping-pong: lin0 -> h16, gather h16->B, fin_lin B->h16)
    lin0_kernel<<<nblk64, 256>>>(x, W0, as0, ad0, N);
    gather_kernel<<<gblk, 256>>>(b0, N);
    fin_lin_kernel<<<nblk128, 256>>>(W1, as1, ad1, N);
    gather_kernel<<<gblk, 256>>>(b1, N);
    fin_lin_kernel<<<nblk128, 256>>>(W2, as2, ad2, N);
    gather_kernel<<<gblk, 256>>>(b2, N);

    // heads (read g_hB)
    fin_last_kernel<<<nblk128, 128>>>(out_w, out_b, batch, out1, N);
    vn_mlp_kernel<<<1, 512>>>(vn_emb0, m1_w1, m1_b1, m1_w2, m1_b2,
                              mf_w1, mf_b1, mf_w2, mf_b2, outvn);
}